// round 8
// baseline (speedup 1.0000x reference)
#include <cuda_runtime.h>
#include <cuda_fp16.h>
#include <cstdint>

#define Ndim 1024
#define Mdim 1024
#define Tdim 64
#define Ddim 128

#define BN 64
#define BM 64
#define BT 2
#define PADK 136          // smem row stride in halves (272B = 68 words: conflict-free)
#define THREADS 128

#define A_BYTES (BT * BN * PADK * 2)      // 34816
#define B_BYTES (BT * BM * PADK * 2)      // 34816
#define SMEM_TOTAL (A_BYTES + B_BYTES)    // 69632 -> 3 CTAs/SM
#define STAGE_T_STRIDE (BN * 66)          // floats per t-plane in epilogue overlay

__device__ float  g_s1[Ndim * Tdim];
__device__ float  g_s2[Mdim * Tdim];
__device__ __half g_h1[(size_t)Ndim * Tdim * Ddim];
__device__ __half g_h2[(size_t)Mdim * Tdim * Ddim];

// ---------------- helpers ----------------
__device__ __forceinline__ uint32_t smem_u32(const void* p) {
    uint32_t a;
    asm("{ .reg .u64 t; cvta.to.shared.u64 t, %1; cvt.u32.u64 %0, t; }" : "=r"(a) : "l"(p));
    return a;
}
__device__ __forceinline__ void cp_async16(uint32_t dst, const void* src) {
    asm volatile("cp.async.cg.shared.global [%0], [%1], 16;" :: "r"(dst), "l"(src));
}
__device__ __forceinline__ void cp_commit() {
    asm volatile("cp.async.commit_group;" ::: "memory");
}
template <int N>
__device__ __forceinline__ void cp_wait() {
    asm volatile("cp.async.wait_group %0;" :: "n"(N) : "memory");
}

__device__ __forceinline__ void mma16816(float* c, uint32_t a0, uint32_t a1,
                                         uint32_t a2, uint32_t a3,
                                         uint32_t b0, uint32_t b1) {
    asm volatile(
        "mma.sync.aligned.m16n8k16.row.col.f32.f16.f16.f32 "
        "{%0,%1,%2,%3}, {%4,%5,%6,%7}, {%8,%9}, {%0,%1,%2,%3};\n"
        : "+f"(c[0]), "+f"(c[1]), "+f"(c[2]), "+f"(c[3])
        : "r"(a0), "r"(a1), "r"(a2), "r"(a3), "r"(b0), "r"(b1));
}

// ---------------------------------------------------------------------------
// Kernel 1: fused fp16 convert + squared row norms. One warp per (row, t).
// ---------------------------------------------------------------------------
__global__ void prep_kernel(const float* __restrict__ X1,
                            const float* __restrict__ X2) {
    int gwarp = (blockIdx.x * blockDim.x + threadIdx.x) >> 5;
    int lane  = threadIdx.x & 31;
    const float* src;
    float* ndst;
    __half* hdst;
    int row;
    if (gwarp < Ndim * Tdim) { src = X1; ndst = g_s1; hdst = g_h1; row = gwarp; }
    else                     { src = X2; ndst = g_s2; hdst = g_h2; row = gwarp - Ndim * Tdim; }
    const float4 v = *((const float4*)(src + (size_t)row * Ddim) + lane);
    __half2 h01 = __floats2half2_rn(v.x, v.y);
    __half2 h23 = __floats2half2_rn(v.z, v.w);
    uint2 packed;
    packed.x = *(uint32_t*)&h01;
    packed.y = *(uint32_t*)&h23;
    *(uint2*)(hdst + (size_t)row * Ddim + lane * 4) = packed;
    float s = v.x * v.x + v.y * v.y + v.z * v.z + v.w * v.w;
    #pragma unroll
    for (int o = 16; o > 0; o >>= 1) s += __shfl_down_sync(0xffffffffu, s, o);
    if (lane == 0) ndst[row] = s;
}

// ---------------------------------------------------------------------------
// Kernel 2: batched cross-GEMM via mma.sync. Full K resident in smem,
// barrier-free mainloop, 3 CTAs/SM for inter-CTA latency hiding.
// CTA: 128 threads = 4 warps = 2 t-planes x 2 m-halves.
// CTA tile: 64n x 64m x 2t. Warp tile: 64n x 32m (one t), K=128 unrolled.
// ---------------------------------------------------------------------------
__global__ __launch_bounds__(THREADS, 3)
void cross_mma_kernel(float* __restrict__ Y) {
    extern __shared__ char smem[];
    const uint32_t sbase = smem_u32(smem);

    const int tid  = threadIdx.x;
    const int lane = tid & 31;
    const int wid  = tid >> 5;
    const int tp   = wid >> 1;   // t-plane 0..1
    const int mh   = wid & 1;    // m-half 0..1

    const int t0 = blockIdx.x * BT;       // t fastest: sector merge across CTAs
    const int m0 = blockIdx.y * BM;
    const int n0 = blockIdx.z * BN;

    const int lr = lane >> 2;          // 0..7
    const int lc = (lane & 3) * 2;     // 0,2,4,6

    // ---- single cp.async burst: full K for A and B tiles ----
    // A: 2t x 64n x 128k halves = 2048 float4 ; B same. 32 per thread.
    {
        #pragma unroll
        for (int it = 0; it < 32; ++it) {
            int i = tid + it * THREADS;          // 0..4095
            if (i < 2048) {
                int k4 = i & 15, n = (i >> 4) & 63, t = i >> 10;
                const __half* g = g_h1 + ((size_t)(n0 + n) * Tdim + (t0 + t)) * Ddim + k4 * 8;
                cp_async16(sbase + (t * BN + n) * (PADK * 2) + k4 * 16, g);
            } else {
                int j = i - 2048;
                int k4 = j & 15, m = (j >> 4) & 63, t = j >> 10;
                const __half* g = g_h2 + ((size_t)(m0 + m) * Tdim + (t0 + t)) * Ddim + k4 * 8;
                cp_async16(sbase + A_BYTES + (t * BM + m) * (PADK * 2) + k4 * 16, g);
            }
        }
        cp_commit();
    }

    float acc[4][4][4];
    #pragma unroll
    for (int i = 0; i < 4; ++i)
        #pragma unroll
        for (int j = 0; j < 4; ++j)
            #pragma unroll
            for (int q = 0; q < 4; ++q) acc[i][j][q] = 0.0f;

    cp_wait<0>();
    __syncthreads();      // the ONLY mainloop barrier

    const __half* Ah = (const __half*)(smem) + tp * (BN * PADK);
    const __half* Bh = (const __half*)(smem + A_BYTES) + tp * (BM * PADK);

    #pragma unroll
    for (int s = 0; s < 8; ++s) {        // eight k16 steps, K=128
        const int kb = s * 16;
        uint32_t b0[4], b1[4];
        #pragma unroll
        for (int mi = 0; mi < 4; ++mi) {
            const __half* bp = Bh + (mh * 32 + mi * 8 + lr) * PADK + kb + lc;
            b0[mi] = *(const uint32_t*)(bp);
            b1[mi] = *(const uint32_t*)(bp + 8);
        }
        #pragma unroll
        for (int ni = 0; ni < 4; ++ni) {
            const __half* ap = Ah + (ni * 16 + lr) * PADK + kb + lc;
            uint32_t a0 = *(const uint32_t*)(ap);
            uint32_t a1 = *(const uint32_t*)(ap + 8 * PADK);
            uint32_t a2 = *(const uint32_t*)(ap + 8);
            uint32_t a3 = *(const uint32_t*)(ap + 8 * PADK + 8);
            #pragma unroll
            for (int mi = 0; mi < 4; ++mi)
                mma16816(acc[ni][mi], a0, a1, a2, a3, b0[mi], b1[mi]);
        }
    }
    __syncthreads();      // compute done; smem reusable as epilogue stage

    // ---- epilogue: combine with norms, stage [t][n][66] in smem ----
    const float invD = 1.0f / (float)Ddim;
    const int tt = t0 + tp;
    float s1a[4], s1b[4], s2a[4], s2b[4];
    #pragma unroll
    for (int ni = 0; ni < 4; ++ni) {
        s1a[ni] = __ldg(&g_s1[(n0 + ni * 16 + lr) * Tdim + tt]);
        s1b[ni] = __ldg(&g_s1[(n0 + ni * 16 + lr + 8) * Tdim + tt]);
    }
    #pragma unroll
    for (int mi = 0; mi < 4; ++mi) {
        int mg = m0 + mh * 32 + mi * 8 + lc;
        s2a[mi] = __ldg(&g_s2[mg * Tdim + tt]);
        s2b[mi] = __ldg(&g_s2[(mg + 1) * Tdim + tt]);
    }

    float* stage = (float*)smem;
    float* plane = stage + tp * STAGE_T_STRIDE;
    #pragma unroll
    for (int ni = 0; ni < 4; ++ni) {
        #pragma unroll
        for (int mi = 0; mi < 4; ++mi) {
            int r  = ni * 16 + lr;
            int m2 = mh * 32 + mi * 8 + lc;
            float2 v0, v1;
            v0.x = (s1a[ni] + s2a[mi] - 2.0f * acc[ni][mi][0]) * invD;
            v0.y = (s1a[ni] + s2b[mi] - 2.0f * acc[ni][mi][1]) * invD;
            v1.x = (s1b[ni] + s2a[mi] - 2.0f * acc[ni][mi][2]) * invD;
            v1.y = (s1b[ni] + s2b[mi] - 2.0f * acc[ni][mi][3]) * invD;
            *(float2*)(plane + r * 66 + m2)       = v0;
            *(float2*)(plane + (r + 8) * 66 + m2) = v1;
        }
    }
    __syncthreads();

    // ---- writeback: 8B (2 t's) per (n,m); 4 adjacent-t CTAs fill a sector ----
    #pragma unroll
    for (int it = 0; it < 32; ++it) {
        int p = tid + it * THREADS;    // 0..4095
        int n = p >> 6;
        int m = p & 63;
        float2 w;
        w.x = stage[0 * STAGE_T_STRIDE + n * 66 + m];
        w.y = stage[1 * STAGE_T_STRIDE + n * 66 + m];
        size_t off = ((size_t)(n0 + n) * Mdim + (m0 + m)) * Tdim + t0;
        *(float2*)(Y + off) = w;
    }
}

// ---------------------------------------------------------------------------
extern "C" void kernel_launch(void* const* d_in, const int* in_sizes, int n_in,
                              void* d_out, int out_size) {
    const float* X1 = (const float*)d_in[0];
    const float* X2 = (const float*)d_in[1];
    float* Y = (float*)d_out;

    int total_warps = 2 * Ndim * Tdim;
    int blocks = (total_warps * 32) / 256;
    prep_kernel<<<blocks, 256>>>(X1, X2);

    cudaFuncSetAttribute(cross_mma_kernel,
                         cudaFuncAttributeMaxDynamicSharedMemorySize, SMEM_TOTAL);
    dim3 grid(Tdim / BT, Mdim / BM, Ndim / BN);   // 32 x 16 x 16, t fastest
    cross_mma_kernel<<<grid, THREADS, SMEM_TOTAL>>>(Y);
}

// round 9
// speedup vs baseline: 1.2441x; 1.2441x over previous
#include <cuda_runtime.h>
#include <cuda_fp16.h>
#include <cstdint>

#define Ndim 1024
#define Mdim 1024
#define Tdim 64
#define Ddim 128

#define BN 64
#define BM 64
#define BT 4
#define KC 32            // halves per K chunk
#define NKC (Ddim / KC)  // 4
#define PADK 40          // smem row stride in halves (80B; ldmatrix conflict-free)
#define THREADS 256

#define A_STAGE_BYTES (BT * BN * PADK * 2)   // 20480
#define PIPE_BYTES (2 * A_STAGE_BYTES)       // 40960
#define EPI_BYTES (BT * BN * 66 * 4)         // 67584 (epilogue overlay)
#define SMEM_TOTAL 69632
#define STAGE_T_STRIDE (BN * 66)             // floats per t-plane

__device__ float  g_s1[Ndim * Tdim];
__device__ float  g_s2[Mdim * Tdim];
__device__ __half g_h1[(size_t)Ndim * Tdim * Ddim];
__device__ __half g_h2[(size_t)Mdim * Tdim * Ddim];

// ---------------- helpers ----------------
__device__ __forceinline__ uint32_t smem_u32(const void* p) {
    uint32_t a;
    asm("{ .reg .u64 t; cvta.to.shared.u64 t, %1; cvt.u32.u64 %0, t; }" : "=r"(a) : "l"(p));
    return a;
}
__device__ __forceinline__ void cp_async16(uint32_t dst, const void* src) {
    asm volatile("cp.async.cg.shared.global [%0], [%1], 16;" :: "r"(dst), "l"(src));
}
__device__ __forceinline__ void cp_commit() {
    asm volatile("cp.async.commit_group;" ::: "memory");
}
template <int N>
__device__ __forceinline__ void cp_wait() {
    asm volatile("cp.async.wait_group %0;" :: "n"(N) : "memory");
}
__device__ __forceinline__ void ldmatrix_x4(uint32_t& r0, uint32_t& r1,
                                            uint32_t& r2, uint32_t& r3, uint32_t addr) {
    asm volatile("ldmatrix.sync.aligned.m8n8.x4.shared.b16 {%0,%1,%2,%3}, [%4];"
        : "=r"(r0), "=r"(r1), "=r"(r2), "=r"(r3) : "r"(addr));
}
__device__ __forceinline__ void mma16816(float* c, uint32_t a0, uint32_t a1,
                                         uint32_t a2, uint32_t a3,
                                         uint32_t b0, uint32_t b1) {
    asm volatile(
        "mma.sync.aligned.m16n8k16.row.col.f32.f16.f16.f32 "
        "{%0,%1,%2,%3}, {%4,%5,%6,%7}, {%8,%9}, {%0,%1,%2,%3};\n"
        : "+f"(c[0]), "+f"(c[1]), "+f"(c[2]), "+f"(c[3])
        : "r"(a0), "r"(a1), "r"(a2), "r"(a3), "r"(b0), "r"(b1));
}

// ---------------------------------------------------------------------------
// Kernel 1: fused fp16 convert + squared row norms. One warp per (row, t).
// ---------------------------------------------------------------------------
__global__ void prep_kernel(const float* __restrict__ X1,
                            const float* __restrict__ X2) {
    int gwarp = (blockIdx.x * blockDim.x + threadIdx.x) >> 5;
    int lane  = threadIdx.x & 31;
    const float* src;
    float* ndst;
    __half* hdst;
    int row;
    if (gwarp < Ndim * Tdim) { src = X1; ndst = g_s1; hdst = g_h1; row = gwarp; }
    else                     { src = X2; ndst = g_s2; hdst = g_h2; row = gwarp - Ndim * Tdim; }
    const float4 v = *((const float4*)(src + (size_t)row * Ddim) + lane);
    __half2 h01 = __floats2half2_rn(v.x, v.y);
    __half2 h23 = __floats2half2_rn(v.z, v.w);
    uint2 packed;
    packed.x = *(uint32_t*)&h01;
    packed.y = *(uint32_t*)&h23;
    *(uint2*)(hdst + (size_t)row * Ddim + lane * 4) = packed;
    float s = v.x * v.x + v.y * v.y + v.z * v.z + v.w * v.w;
    #pragma unroll
    for (int o = 16; o > 0; o >>= 1) s += __shfl_down_sync(0xffffffffu, s, o);
    if (lane == 0) ndst[row] = s;
}

// ---------------------------------------------------------------------------
// Kernel 2: batched cross-GEMM via mma.sync.
// A staged in smem (double buffer, ldmatrix). B fed straight from L2 via
// LDG.32, double-buffered one kstep ahead (each B element used by 1 warp).
// CTA: 256 threads = 8 warps = 4 t-planes x 2 m-halves, 2 CTAs/SM.
// ---------------------------------------------------------------------------
__global__ __launch_bounds__(THREADS, 2)
void cross_mma_kernel(float* __restrict__ Y) {
    extern __shared__ char smem[];
    const uint32_t sbase = smem_u32(smem);

    const int tid  = threadIdx.x;
    const int lane = tid & 31;
    const int wid  = tid >> 5;
    const int tp   = wid >> 1;   // t-plane 0..3
    const int mh   = wid & 1;    // m-half 0..1

    const int t0 = blockIdx.x * BT;    // t fastest: sector merge across CTAs
    const int m0 = blockIdx.y * BM;
    const int n0 = blockIdx.z * BN;

    const int lr = lane >> 2;          // 0..7
    const int lc = (lane & 3) * 2;     // 0,2,4,6
    const int tt = t0 + tp;

    // ldmatrix per-lane offset: mat = lane>>3; mats ordered (r0-7,k0-7),
    // (r8-15,k0-7), (r0-7,k8-15), (r8-15,k8-15)
    const int mrow = (lane & 7) + ((lane >> 3) & 1) * 8;
    const int mk   = (lane >> 4) * 8;
    const uint32_t a_lane_off = (uint32_t)((mrow * PADK + mk) * 2);

    // B global pointers per mi (lane-resolved)
    const __half* pb[4];
    #pragma unroll
    for (int mi = 0; mi < 4; ++mi)
        pb[mi] = g_h2 + ((size_t)(m0 + mh * 32 + mi * 8 + lr) * Tdim + tt) * Ddim + lc;

    float acc[4][4][4];
    #pragma unroll
    for (int i = 0; i < 4; ++i)
        #pragma unroll
        for (int j = 0; j < 4; ++j)
            #pragma unroll
            for (int q = 0; q < 4; ++q) acc[i][j][q] = 0.0f;

    // ---- A-only cp.async loader: 1024 float4 per stage / 256 thr = 4 ----
    auto load_stage = [&](int cc, int buf) {
        const uint32_t abase = sbase + buf * A_STAGE_BYTES;
        #pragma unroll
        for (int it = 0; it < 4; ++it) {
            int i = tid + it * THREADS;          // 0..1023
            int k4 = i & 3, n = (i >> 2) & 63, t = i >> 8;
            const __half* g = g_h1 + ((size_t)(n0 + n) * Tdim + (t0 + t)) * Ddim
                              + cc * KC + k4 * 8;
            cp_async16(abase + t * (BN * PADK * 2) + n * (PADK * 2) + k4 * 16, g);
        }
        cp_commit();
    };

    // B fragment double buffer (kstep parity is compile-time)
    uint32_t bf[2][4][2];
    #pragma unroll
    for (int mi = 0; mi < 4; ++mi) {
        bf[0][mi][0] = *(const uint32_t*)(pb[mi]);
        bf[0][mi][1] = *(const uint32_t*)(pb[mi] + 8);
    }

    load_stage(0, 0);

    for (int cc = 0; cc < NKC; ++cc) {
        if (cc + 1 < NKC) {
            load_stage(cc + 1, (cc + 1) & 1);
            cp_wait<1>();
        } else {
            cp_wait<0>();
        }
        __syncthreads();      // chunk cc's A visible

        const uint32_t abuf = sbase + (cc & 1) * A_STAGE_BYTES
                              + tp * (BN * PADK * 2) + a_lane_off;

        #pragma unroll
        for (int ks = 0; ks < 2; ++ks) {      // g = cc*2 + ks ; g&1 == ks
            const int g = cc * 2 + ks;
            if (g < 7) {                       // prefetch next kstep's B
                #pragma unroll
                for (int mi = 0; mi < 4; ++mi) {
                    bf[1 - ks][mi][0] = *(const uint32_t*)(pb[mi] + (g + 1) * 16);
                    bf[1 - ks][mi][1] = *(const uint32_t*)(pb[mi] + (g + 1) * 16 + 8);
                }
            }
            uint32_t af[4][4];
            #pragma unroll
            for (int ni = 0; ni < 4; ++ni)
                ldmatrix_x4(af[ni][0], af[ni][1], af[ni][2], af[ni][3],
                            abuf + ni * (16 * PADK * 2) + ks * 32);
            #pragma unroll
            for (int ni = 0; ni < 4; ++ni)
                #pragma unroll
                for (int mi = 0; mi < 4; ++mi)
                    mma16816(acc[ni][mi], af[ni][0], af[ni][1], af[ni][2], af[ni][3],
                             bf[ks][mi][0], bf[ks][mi][1]);
        }
        __syncthreads();      // all warps done with A buf before overwrite
    }

    // ---- epilogue: combine with norms, stage [t][n][66] in smem ----
    const float invD = 1.0f / (float)Ddim;
    float s1a[4], s1b[4], s2a[4], s2b[4];
    #pragma unroll
    for (int ni = 0; ni < 4; ++ni) {
        s1a[ni] = __ldg(&g_s1[(n0 + ni * 16 + lr) * Tdim + tt]);
        s1b[ni] = __ldg(&g_s1[(n0 + ni * 16 + lr + 8) * Tdim + tt]);
    }
    #pragma unroll
    for (int mi = 0; mi < 4; ++mi) {
        int mg = m0 + mh * 32 + mi * 8 + lc;
        s2a[mi] = __ldg(&g_s2[mg * Tdim + tt]);
        s2b[mi] = __ldg(&g_s2[(mg + 1) * Tdim + tt]);
    }

    float* stage = (float*)smem;
    float* plane = stage + tp * STAGE_T_STRIDE;
    #pragma unroll
    for (int ni = 0; ni < 4; ++ni) {
        #pragma unroll
        for (int mi = 0; mi < 4; ++mi) {
            int r  = ni * 16 + lr;
            int m2 = mh * 32 + mi * 8 + lc;
            float2 v0, v1;
            v0.x = (s1a[ni] + s2a[mi] - 2.0f * acc[ni][mi][0]) * invD;
            v0.y = (s1a[ni] + s2b[mi] - 2.0f * acc[ni][mi][1]) * invD;
            v1.x = (s1b[ni] + s2a[mi] - 2.0f * acc[ni][mi][2]) * invD;
            v1.y = (s1b[ni] + s2b[mi] - 2.0f * acc[ni][mi][3]) * invD;
            *(float2*)(plane + r * 66 + m2)       = v0;
            *(float2*)(plane + (r + 8) * 66 + m2) = v1;
        }
    }
    __syncthreads();

    // ---- writeback: 16B (4 t's) per (n,m); adjacent-t CTA fills the sector ----
    #pragma unroll
    for (int it = 0; it < 16; ++it) {
        int p = tid + it * THREADS;    // 0..4095
        int n = p >> 6;
        int m = p & 63;
        float4 w;
        w.x = stage[0 * STAGE_T_STRIDE + n * 66 + m];
        w.y = stage[1 * STAGE_T_STRIDE + n * 66 + m];
        w.z = stage[2 * STAGE_T_STRIDE + n * 66 + m];
        w.w = stage[3 * STAGE_T_STRIDE + n * 66 + m];
        size_t off = ((size_t)(n0 + n) * Mdim + (m0 + m)) * Tdim + t0;
        *(float4*)(Y + off) = w;
    }
}

// ---------------------------------------------------------------------------
extern "C" void kernel_launch(void* const* d_in, const int* in_sizes, int n_in,
                              void* d_out, int out_size) {
    const float* X1 = (const float*)d_in[0];
    const float* X2 = (const float*)d_in[1];
    float* Y = (float*)d_out;

    int total_warps = 2 * Ndim * Tdim;
    int blocks = (total_warps * 32) / 256;
    prep_kernel<<<blocks, 256>>>(X1, X2);

    cudaFuncSetAttribute(cross_mma_kernel,
                         cudaFuncAttributeMaxDynamicSharedMemorySize, SMEM_TOTAL);
    dim3 grid(Tdim / BT, Mdim / BM, Ndim / BN);   // 16 x 16 x 16, t fastest
    cross_mma_kernel<<<grid, THREADS, SMEM_TOTAL>>>(Y);
}